// round 3
// baseline (speedup 1.0000x reference)
#include <cuda_runtime.h>
#include <cstdint>

// Problem constants
#define Bsz 8
#define Tt  512
#define Dd  1024
#define Hh  16
#define DHh 64
#define Ll  4
#define Cc  10
#define Mrows (Bsz*Tt)   // 4096
#define BH   (Bsz*Hh)    // 128
#define INV_RD (1.0f/32.0f)

// ---------------- scratch (static device globals: allocation-free) ----------
__device__ float g_xa[Mrows*Dd];
__device__ float g_xb[Mrows*Dd];
__device__ float g_q [Mrows*Dd];
__device__ float g_k [Mrows*Dd];
__device__ float g_v [Mrows*Dd];
__device__ float g_s [(size_t)BH*Tt*Tt];   // 134 MB scores

// ---------------- add positional encoding --------------------------------
__global__ void add_pos_kernel(const float* __restrict__ x,
                               const float* __restrict__ pos,
                               float* __restrict__ out) {
    int i = blockIdx.x * blockDim.x + threadIdx.x;           // float4 index
    const int n4 = Mrows*Dd/4;
    if (i < n4) {
        float4 a = ((const float4*)x)[i];
        float4 p = ((const float4*)pos)[i % (Tt*Dd/4)];
        a.x += p.x; a.y += p.y; a.z += p.z; a.w += p.w;
        ((float4*)out)[i] = a;
    }
}

// ---------------- layernorm (in-place, one block per row) -----------------
__global__ void ln_kernel(float* __restrict__ x,
                          const float* __restrict__ g,
                          const float* __restrict__ b) {
    __shared__ float red[16];
    __shared__ float s_mv[2];
    int row = blockIdx.x;
    int tid = threadIdx.x;                 // 256 threads, 4 floats each
    float4* xp = (float4*)(x + (size_t)row*Dd);
    float4 v = xp[tid];
    float s  = v.x+v.y+v.z+v.w;
    float sq = v.x*v.x+v.y*v.y+v.z*v.z+v.w*v.w;
    #pragma unroll
    for (int o=16;o;o>>=1){ s += __shfl_down_sync(0xffffffffu,s,o);
                            sq += __shfl_down_sync(0xffffffffu,sq,o); }
    int warp = tid>>5, lane = tid&31;
    if (!lane){ red[warp]=s; red[8+warp]=sq; }
    __syncthreads();
    if (tid < 32){
        float a = (lane<8)? red[lane]   : 0.f;
        float c = (lane<8)? red[8+lane] : 0.f;
        #pragma unroll
        for (int o=4;o;o>>=1){ a += __shfl_down_sync(0xffffffffu,a,o);
                               c += __shfl_down_sync(0xffffffffu,c,o); }
        if (!lane){
            float mean = a * (1.0f/Dd);
            float var  = c * (1.0f/Dd) - mean*mean;
            s_mv[0] = mean;
            s_mv[1] = rsqrtf(var + 1e-5f);
        }
    }
    __syncthreads();
    float mean = s_mv[0], rstd = s_mv[1];
    float4 gg = ((const float4*)g)[tid];
    float4 bb = ((const float4*)b)[tid];
    v.x = (v.x-mean)*rstd*gg.x + bb.x;
    v.y = (v.y-mean)*rstd*gg.y + bb.y;
    v.z = (v.z-mean)*rstd*gg.z + bb.z;
    v.w = (v.w-mean)*rstd*gg.w + bb.w;
    xp[tid] = v;
}

// ---------------- projection GEMM: C[M,N] = A[M,K] @ W[N,K]^T --------------
// M=4096, N=1024, K=1024. 128x128x8 tile, 256 threads, 8x8 microtile.
// FCEPI: C = relu(A@W^T + bias) + A   (residual = A itself, N==K==D)
template<bool FCEPI>
__global__ void __launch_bounds__(256)
gemm_nt(const float* __restrict__ A, const float* __restrict__ W,
        const float* __restrict__ bias, float* __restrict__ C) {
    __shared__ float As[8][132];
    __shared__ float Bs[8][132];
    const int tid = threadIdx.x;
    const int bm = blockIdx.y * 128, bn = blockIdx.x * 128;
    const int tx = tid & 15, ty = tid >> 4;
    const int lr = tid >> 1;              // load row 0..127
    const int lc = (tid & 1) * 4;         // k sub-offset 0 or 4
    const float* Ap = A + (size_t)(bm+lr)*1024 + lc;
    const float* Wp = W + (size_t)(bn+lr)*1024 + lc;
    float acc[8][8] = {};
    for (int k0 = 0; k0 < 1024; k0 += 8) {
        float4 av = *(const float4*)(Ap + k0);
        float4 wv = *(const float4*)(Wp + k0);
        __syncthreads();
        As[lc+0][lr]=av.x; As[lc+1][lr]=av.y; As[lc+2][lr]=av.z; As[lc+3][lr]=av.w;
        Bs[lc+0][lr]=wv.x; Bs[lc+1][lr]=wv.y; Bs[lc+2][lr]=wv.z; Bs[lc+3][lr]=wv.w;
        __syncthreads();
        #pragma unroll
        for (int kk = 0; kk < 8; kk++) {
            float4 a0 = *(const float4*)&As[kk][ty*8];
            float4 a1 = *(const float4*)&As[kk][ty*8+4];
            float4 b0 = *(const float4*)&Bs[kk][tx*8];
            float4 b1 = *(const float4*)&Bs[kk][tx*8+4];
            float a[8] = {a0.x,a0.y,a0.z,a0.w,a1.x,a1.y,a1.z,a1.w};
            float bb[8]= {b0.x,b0.y,b0.z,b0.w,b1.x,b1.y,b1.z,b1.w};
            #pragma unroll
            for (int i=0;i<8;i++)
                #pragma unroll
                for (int j=0;j<8;j++)
                    acc[i][j] += a[i]*bb[j];
        }
    }
    #pragma unroll
    for (int i=0;i<8;i++){
        int row = bm + ty*8 + i;
        #pragma unroll
        for (int j=0;j<8;j+=4){
            int col = bn + tx*8 + j;
            float4 c = make_float4(acc[i][j],acc[i][j+1],acc[i][j+2],acc[i][j+3]);
            if (FCEPI){
                float4 bi = *(const float4*)(bias + col);
                float4 r  = *(const float4*)(A + (size_t)row*1024 + col);
                c.x = fmaxf(c.x+bi.x,0.f)+r.x;
                c.y = fmaxf(c.y+bi.y,0.f)+r.y;
                c.z = fmaxf(c.z+bi.z,0.f)+r.z;
                c.w = fmaxf(c.w+bi.w,0.f)+r.w;
            }
            *(float4*)(C + (size_t)row*1024 + col) = c;
        }
    }
}

// ---------------- attention scores: S[z,q,k] = (Q[q]·K[k])/32 --------------
// grid (T/128=4, T/128=4, BH). 128x128 tile over q,k; BK=32 over e (2 chunks).
template<bool SELF>
__global__ void __launch_bounds__(256)
attn_scores(const float* __restrict__ Q, const float* __restrict__ Kt,
            float* __restrict__ S) {
    __shared__ float Qs[32][132];
    __shared__ float Ks[32][132];
    const int z = blockIdx.z, b = z >> 4, h = z & 15;
    const float* Qb = Q + (size_t)(b*Tt)*Dd + h*DHh;   const int qstr = Dd;
    const float* Kb;  int kstr;
    if (SELF) { Kb = Kt + (size_t)(b*Tt)*Dd + h*DHh; kstr = Dd; }
    else      { Kb = Kt + (size_t)z*Tt*DHh;          kstr = DHh; }
    float* Sb = S + (size_t)z*Tt*Tt;
    const int bq = blockIdx.y*128, bk = blockIdx.x*128;
    const int tid = threadIdx.x, tx = tid & 15, ty = tid >> 4;
    float acc[8][8] = {};
    for (int e0 = 0; e0 < 64; e0 += 32) {
        float4 qv[4], kv[4];
        #pragma unroll
        for (int i=0;i<4;i++){
            int f4 = i*256 + tid; int r = f4 >> 3; int e4 = (f4 & 7) * 4;
            qv[i] = *(const float4*)(Qb + (size_t)(bq+r)*qstr + e0 + e4);
            kv[i] = *(const float4*)(Kb + (size_t)(bk+r)*kstr + e0 + e4);
        }
        __syncthreads();
        #pragma unroll
        for (int i=0;i<4;i++){
            int f4 = i*256 + tid; int r = f4 >> 3; int e4 = (f4 & 7) * 4;
            Qs[e4+0][r]=qv[i].x; Qs[e4+1][r]=qv[i].y; Qs[e4+2][r]=qv[i].z; Qs[e4+3][r]=qv[i].w;
            Ks[e4+0][r]=kv[i].x; Ks[e4+1][r]=kv[i].y; Ks[e4+2][r]=kv[i].z; Ks[e4+3][r]=kv[i].w;
        }
        __syncthreads();
        #pragma unroll
        for (int kk=0;kk<32;kk++){
            float4 a0 = *(const float4*)&Qs[kk][ty*8];
            float4 a1 = *(const float4*)&Qs[kk][ty*8+4];
            float4 b0 = *(const float4*)&Ks[kk][tx*8];
            float4 b1 = *(const float4*)&Ks[kk][tx*8+4];
            float a[8] = {a0.x,a0.y,a0.z,a0.w,a1.x,a1.y,a1.z,a1.w};
            float bb[8]= {b0.x,b0.y,b0.z,b0.w,b1.x,b1.y,b1.z,b1.w};
            #pragma unroll
            for (int i=0;i<8;i++)
                #pragma unroll
                for (int j=0;j<8;j++)
                    acc[i][j] += a[i]*bb[j];
        }
    }
    #pragma unroll
    for (int i=0;i<8;i++){
        int row = bq + ty*8 + i;
        #pragma unroll
        for (int j=0;j<8;j+=4){
            int col = bk + tx*8 + j;
            float4 c = make_float4(acc[i][j]*INV_RD, acc[i][j+1]*INV_RD,
                                   acc[i][j+2]*INV_RD, acc[i][j+3]*INV_RD);
            *(float4*)(Sb + (size_t)row*Tt + col) = c;
        }
    }
}

// ---------------- softmax over rows of S (optional causal mask) ------------
template<bool CAUSAL>
__global__ void softmax_kernel(float* __restrict__ S) {
    const int r = blockIdx.x*8 + (threadIdx.x >> 5);
    const int lane = threadIdx.x & 31;
    float4* row = (float4*)(S + (size_t)r*Tt);
    const int q = r & (Tt-1);
    const float NEG_INF = __int_as_float(0xff800000);
    float4 v[4];
    float m = -3.0e38f;
    #pragma unroll
    for (int w=0; w<4; w++){
        v[w] = row[w*32 + lane];
        if (CAUSAL){
            int c0 = (w*32 + lane)*4;
            if (c0+0 > q) v[w].x = NEG_INF;
            if (c0+1 > q) v[w].y = NEG_INF;
            if (c0+2 > q) v[w].z = NEG_INF;
            if (c0+3 > q) v[w].w = NEG_INF;
        }
        m = fmaxf(m, fmaxf(fmaxf(v[w].x,v[w].y), fmaxf(v[w].z,v[w].w)));
    }
    #pragma unroll
    for (int o=16;o;o>>=1) m = fmaxf(m, __shfl_xor_sync(0xffffffffu,m,o));
    float sum = 0.f;
    #pragma unroll
    for (int w=0; w<4; w++){
        v[w].x = __expf(v[w].x - m);
        v[w].y = __expf(v[w].y - m);
        v[w].z = __expf(v[w].z - m);
        v[w].w = __expf(v[w].w - m);
        sum += v[w].x+v[w].y+v[w].z+v[w].w;
    }
    #pragma unroll
    for (int o=16;o;o>>=1) sum += __shfl_xor_sync(0xffffffffu,sum,o);
    float inv = __frcp_rn(sum);
    #pragma unroll
    for (int w=0; w<4; w++){
        v[w].x*=inv; v[w].y*=inv; v[w].z*=inv; v[w].w*=inv;
        row[w*32 + lane] = v[w];
    }
}

// ---------------- PV: X[b,q,h,:] += P[z] @ V[z]  ---------------------------
// grid (T/128=4, BH). 128x64 out tile, BK=32, 8x4 microtile.
template<bool SELF>
__global__ void __launch_bounds__(256)
attn_pv(const float* __restrict__ S, const float* __restrict__ V,
        float* __restrict__ X) {
    __shared__ float Ps[32][132];
    __shared__ float Vs[32][64];
    const int z = blockIdx.y, b = z >> 4, h = z & 15;
    const float* Pb = S + (size_t)z*Tt*Tt;
    const float* Vb; int vstr;
    if (SELF) { Vb = V + (size_t)(b*Tt)*Dd + h*DHh; vstr = Dd; }
    else      { Vb = V + (size_t)z*Tt*DHh;          vstr = DHh; }
    float* Xb = X + (size_t)(b*Tt)*Dd + h*DHh;
    const int bq = blockIdx.x*128;
    const int tid = threadIdx.x, tx = tid & 15, ty = tid >> 4;
    float acc[8][4] = {};
    for (int k0 = 0; k0 < Tt; k0 += 32) {
        float4 pv4[4]; float4 vv[2];
        #pragma unroll
        for (int i=0;i<4;i++){
            int f4 = i*256 + tid; int r = f4 >> 3; int c4 = (f4 & 7) * 4;
            pv4[i] = *(const float4*)(Pb + (size_t)(bq+r)*Tt + k0 + c4);
        }
        #pragma unroll
        for (int i=0;i<2;i++){
            int f4 = i*256 + tid; int vr = f4 >> 4; int n4 = (f4 & 15) * 4;
            vv[i] = *(const float4*)(Vb + (size_t)(k0+vr)*vstr + n4);
        }
        __syncthreads();
        #pragma unroll
        for (int i=0;i<4;i++){
            int f4 = i*256 + tid; int r = f4 >> 3; int c4 = (f4 & 7) * 4;
            Ps[c4+0][r]=pv4[i].x; Ps[c4+1][r]=pv4[i].y; Ps[c4+2][r]=pv4[i].z; Ps[c4+3][r]=pv4[i].w;
        }
        #pragma unroll
        for (int i=0;i<2;i++){
            int f4 = i*256 + tid; int vr = f4 >> 4; int n4 = (f4 & 15) * 4;
            *(float4*)&Vs[vr][n4] = vv[i];
        }
        __syncthreads();
        #pragma unroll
        for (int kk=0;kk<32;kk++){
            float4 a0 = *(const float4*)&Ps[kk][ty*8];
            float4 a1 = *(const float4*)&Ps[kk][ty*8+4];
            float4 bf = *(const float4*)&Vs[kk][tx*4];
            float a[8] = {a0.x,a0.y,a0.z,a0.w,a1.x,a1.y,a1.z,a1.w};
            float bb[4]= {bf.x,bf.y,bf.z,bf.w};
            #pragma unroll
            for (int i=0;i<8;i++)
                #pragma unroll
                for (int j=0;j<4;j++)
                    acc[i][j] += a[i]*bb[j];
        }
    }
    #pragma unroll
    for (int i=0;i<8;i++){
        int row = bq + ty*8 + i;
        float4* xp = (float4*)(Xb + (size_t)row*Dd + tx*4);
        float4 o = *xp;
        o.x += acc[i][0]; o.y += acc[i][1]; o.z += acc[i][2]; o.w += acc[i][3];
        *xp = o;
    }
}

// ---------------- ordinal sigmoid head ------------------------------------
__global__ void head_kernel(const float* __restrict__ X,
                            const float* __restrict__ cutoff,
                            float* __restrict__ out) {
    __shared__ float E[9];
    if (threadIdx.x < 9) {
        float bj = cutoff[0];
        for (int j=1;j<=threadIdx.x;j++){ float c = cutoff[j]; bj += c*c; }
        E[threadIdx.x] = __expf(-bj);
    }
    __syncthreads();
    const int n = Mrows*Dd;
    for (int idx = blockIdx.x*blockDim.x + threadIdx.x; idx < n;
         idx += gridDim.x*blockDim.x) {
        float xv = X[idx];
        float ex = __expf(xv);
        float s[9];
        #pragma unroll
        for (int j=0;j<9;j++) s[j] = __fdividef(1.0f, 1.0f + ex*E[j]);
        float2* o2 = (float2*)(out + (size_t)idx*10);
        o2[0] = make_float2(s[0],        s[1]-s[0]);
        o2[1] = make_float2(s[2]-s[1],   s[3]-s[2]);
        o2[2] = make_float2(s[4]-s[3],   s[5]-s[4]);
        o2[3] = make_float2(s[6]-s[5],   s[7]-s[6]);
        o2[4] = make_float2(s[8]-s[7],   1.0f - s[8]);
    }
}

// ---------------- launcher --------------------------------------------------
extern "C" void kernel_launch(void* const* d_in, const int* in_sizes, int n_in,
                              void* d_out, int out_size) {
    (void)in_sizes; (void)n_in; (void)out_size;
    const float* x    = (const float*)d_in[0];
    const float* k    = (const float*)d_in[1];
    const float* v    = (const float*)d_in[2];
    const float* pos  = (const float*)d_in[3];
    const float* Wq1  = (const float*)d_in[4];
    const float* Wk1  = (const float*)d_in[5];
    const float* Wv1  = (const float*)d_in[6];
    const float* Wq2  = (const float*)d_in[7];
    const float* Wfc  = (const float*)d_in[8];
    const float* bfc  = (const float*)d_in[9];
    const float* g1   = (const float*)d_in[10];
    const float* b1   = (const float*)d_in[11];
    const float* g2   = (const float*)d_in[12];
    const float* b2   = (const float*)d_in[13];
    const float* g3   = (const float*)d_in[14];
    const float* b3   = (const float*)d_in[15];
    const float* cut  = (const float*)d_in[16];
    float* out = (float*)d_out;

    float *xa, *xb, *q, *kk, *vv, *S;
    cudaGetSymbolAddress((void**)&xa, g_xa);
    cudaGetSymbolAddress((void**)&xb, g_xb);
    cudaGetSymbolAddress((void**)&q,  g_q);
    cudaGetSymbolAddress((void**)&kk, g_k);
    cudaGetSymbolAddress((void**)&vv, g_v);
    cudaGetSymbolAddress((void**)&S,  g_s);

    add_pos_kernel<<<Mrows*Dd/4/256, 256>>>(x, pos, xa);

    float* cur = xa; float* oth = xb;
    const dim3 gGemm(8, 32);
    const dim3 gScores(4, 4, BH);
    const dim3 gPV(4, BH);
    const int gSoft = BH*Tt/8;

    for (int i = 0; i < Ll; i++) {
        if (i) ln_kernel<<<Mrows,256>>>(cur, g1 + (size_t)(i-1)*Dd, b1 + (size_t)(i-1)*Dd);
        // self-attention
        gemm_nt<false><<<gGemm,256>>>(cur, Wq1 + (size_t)i*Dd*Dd, nullptr, q);
        gemm_nt<false><<<gGemm,256>>>(cur, Wk1 + (size_t)i*Dd*Dd, nullptr, kk);
        gemm_nt<false><<<gGemm,256>>>(cur, Wv1 + (size_t)i*Dd*Dd, nullptr, vv);
        attn_scores<true><<<gScores,256>>>(q, kk, S);
        softmax_kernel<false><<<gSoft,256>>>(S);
        attn_pv<true><<<gPV,256>>>(S, vv, cur);
        ln_kernel<<<Mrows,256>>>(cur, g2 + (size_t)i*Dd, b2 + (size_t)i*Dd);
        // cross-attention (causal)
        gemm_nt<false><<<gGemm,256>>>(cur, Wq2 + (size_t)i*Dd*Dd, nullptr, q);
        attn_scores<false><<<gScores,256>>>(q, k, S);
        softmax_kernel<true><<<gSoft,256>>>(S);
        attn_pv<false><<<gPV,256>>>(S, v, cur);
        ln_kernel<<<Mrows,256>>>(cur, g3 + (size_t)i*Dd, b3 + (size_t)i*Dd);
        // FC + relu + residual (ping-pong to avoid read/write race)
        gemm_nt<true><<<gGemm,256>>>(cur, Wfc + (size_t)i*Dd*Dd, bfc + (size_t)i*Dd, oth);
        float* t = cur; cur = oth; oth = t;
    }

    head_kernel<<<4096,256>>>(cur, cut, out);
}